// round 5
// baseline (speedup 1.0000x reference)
#include <cuda_runtime.h>
#include <cuda_bf16.h>
#include <math.h>
#include <stdint.h>

// Problem constants
#define BB   2
#define SS   2048
#define DD   4096
#define QH   32
#define KVH  8
#define HD   128
#define KVD  (KVH*HD)      // 1024
#define GROUP (QH/KVH)     // 4
#define TOK  (BB*SS)       // 4096
#define K3   (3*DD)        // 12288
#define NQKV (DD + 2*KVD)  // 6144

#define QSCALE (0.08838834764831845f * 1.4426950408889634f)

// ---------------------------------------------------------------------------
// Scratch
// ---------------------------------------------------------------------------
__device__ __align__(16) __nv_bfloat16 g_xc  [TOK*K3];
__device__ __align__(16) __nv_bfloat16 g_wqkv[(size_t)NQKV*K3];
__device__ __align__(16) __nv_bfloat16 g_woc [DD*K3];
__device__ __align__(16) __nv_bfloat16 g_cc  [TOK*K3];

__device__ __align__(16) __nv_bfloat16 g_qh[TOK*DD];
__device__ __align__(16) __nv_bfloat16 g_ql[TOK*DD];
__device__ __align__(16) __nv_bfloat16 g_kh[TOK*KVD];
__device__ __align__(16) __nv_bfloat16 g_kl[TOK*KVD];
__device__ __align__(16) __nv_bfloat16 g_vh[TOK*KVD];
__device__ __align__(16) __nv_bfloat16 g_vl[TOK*KVD];

// ---------------------------------------------------------------------------
// helpers
// ---------------------------------------------------------------------------
__device__ __forceinline__ uint32_t smem_u32(const void* p) {
    uint32_t a;
    asm("{ .reg .u64 t; cvta.to.shared.u64 t, %1; cvt.u32.u64 %0, t; }" : "=r"(a) : "l"(p));
    return a;
}

#define CP_ASYNC16(dst, src) \
    asm volatile("cp.async.cg.shared.global [%0], [%1], 16;" :: "r"(dst), "l"(src))
#define CP_COMMIT()   asm volatile("cp.async.commit_group;" ::: "memory")
#define CP_WAIT(n)    asm volatile("cp.async.wait_group %0;" :: "n"(n) : "memory")

#define LDM_X4(r0, r1, r2, r3, addr) \
    asm volatile("ldmatrix.sync.aligned.m8n8.x4.shared.b16 {%0,%1,%2,%3}, [%4];" \
        : "=r"(r0), "=r"(r1), "=r"(r2), "=r"(r3) : "r"(addr))

#define LDM_X4T(r0, r1, r2, r3, addr) \
    asm volatile("ldmatrix.sync.aligned.m8n8.x4.trans.shared.b16 {%0,%1,%2,%3}, [%4];" \
        : "=r"(r0), "=r"(r1), "=r"(r2), "=r"(r3) : "r"(addr))

#define MMA16816(d, a, b) \
    asm volatile("mma.sync.aligned.m16n8k16.row.col.f32.bf16.bf16.f32 " \
        "{%0,%1,%2,%3},{%4,%5,%6,%7},{%8,%9},{%0,%1,%2,%3};" \
        : "+f"((d)[0]), "+f"((d)[1]), "+f"((d)[2]), "+f"((d)[3]) \
        : "r"((a)[0]), "r"((a)[1]), "r"((a)[2]), "r"((a)[3]), \
          "r"((b)[0]), "r"((b)[1]))

__device__ __forceinline__ uint32_t pack_bf16(float a, float b) {
    uint32_t d;
    asm("cvt.rn.bf16x2.f32 %0, %1, %2;" : "=r"(d) : "f"(b), "f"(a));
    return d;
}
__device__ __forceinline__ float ex2f(float x) {
    float r; asm("ex2.approx.f32 %0, %1;" : "=f"(r) : "f"(x)); return r;
}

// ---------------------------------------------------------------------------
// fp32 -> 3-term bf16 split (concatenated K)
// mode 0 (A-form): [hi | lo | hi]   mode 1 (B-form): [hi | hi | lo]
// ---------------------------------------------------------------------------
__global__ void split_bf16_kernel(const float* __restrict__ in,
                                  __nv_bfloat16* __restrict__ out,
                                  int K, int total4, int mode)
{
    int idx = blockIdx.x * blockDim.x + threadIdx.x;
    if (idx >= total4) return;
    float4 v = ((const float4*)in)[idx];
    int K4 = K >> 2;
    int r  = idx / K4;
    int k  = (idx - r * K4) << 2;
    float vv[4] = {v.x, v.y, v.z, v.w};
    __nv_bfloat16 h[4], l[4];
#pragma unroll
    for (int i = 0; i < 4; i++) {
        h[i] = __float2bfloat16(vv[i]);
        l[i] = __float2bfloat16(vv[i] - __bfloat162float(h[i]));
    }
    __nv_bfloat16* row = out + (size_t)r * (3*K);
    if (mode == 0) {
        *(uint2*)(row + k)       = *(uint2*)h;
        *(uint2*)(row + K + k)   = *(uint2*)l;
        *(uint2*)(row + 2*K + k) = *(uint2*)h;
    } else {
        *(uint2*)(row + k)       = *(uint2*)h;
        *(uint2*)(row + K + k)   = *(uint2*)h;
        *(uint2*)(row + 2*K + k) = *(uint2*)l;
    }
}

// ---------------------------------------------------------------------------
// Big-tile bf16 MMA GEMM: C[M,N] = A[M,K3] @ B[N,K3]^T (+epilogue)
// CTA 256x128, BK=32, 256 threads (8 warps, 4m x 2n of 64x64), 4 stages.
// MODE 0: fp32 C = acc + bias       (out projection)
// MODE 1: fused QKV epilogue: route by column, rope for q/k, hi/lo bf16 split.
// ---------------------------------------------------------------------------
#define CT2M   256
#define CT2N   128
#define G2BK   32
#define N2ST   4
#define N2CH   (K3 / G2BK)          // 384
#define ROWB2  80
#define ATILE2 (CT2M * ROWB2)       // 20480
#define BTILE2 (CT2N * ROWB2)       // 10240
#define STAGE2 (ATILE2 + BTILE2)    // 30720
#define GSMEM2 (N2ST * STAGE2)      // 122880

template<int MODE>
__global__ __launch_bounds__(256, 1) void gemm_big(
    const __nv_bfloat16* __restrict__ A, const __nv_bfloat16* __restrict__ B,
    const float* __restrict__ bq, const float* __restrict__ bk,
    const float* __restrict__ bv,
    float* __restrict__ C, int N,
    const float* __restrict__ fc, const int* __restrict__ spos,
    __nv_bfloat16* __restrict__ qh, __nv_bfloat16* __restrict__ ql,
    __nv_bfloat16* __restrict__ kh, __nv_bfloat16* __restrict__ kl,
    __nv_bfloat16* __restrict__ vh, __nv_bfloat16* __restrict__ vl)
{
    extern __shared__ char smraw[];
    const int t    = threadIdx.x;
    const int lane = t & 31;
    const int wid  = t >> 5;
    const int wm   = wid & 3;            // 0..3 (M, 64 rows each)
    const int wn   = wid >> 2;           // 0..1 (N, 64 cols each)
    const int m0   = blockIdx.x * CT2M;
    const int n0   = blockIdx.y * CT2N;
    const uint32_t sb = smem_u32(smraw);

    float acc[4][8][4];
#pragma unroll
    for (int i = 0; i < 4; i++)
#pragma unroll
        for (int j = 0; j < 8; j++)
#pragma unroll
            for (int r = 0; r < 4; r++) acc[i][j][r] = 0.f;

    // 6 cp.async chunks per thread per stage (A: 256 rows, B: 128 rows, 4x16B each)
    const __nv_bfloat16* gsrc[6];
    uint32_t doff[6];
#pragma unroll
    for (int i = 0; i < 6; i++) {
        int id  = t + i * 256;
        int row = id >> 2;
        int c4  = id & 3;
        doff[i] = row * ROWB2 + c4 * 16;
        gsrc[i] = (row < CT2M)
                ? A + (size_t)(m0 + row) * K3 + c4 * 8
                : B + (size_t)(n0 + row - CT2M) * K3 + c4 * 8;
    }

#define LOAD_STG(st, k0) do {                                          \
    uint32_t base = sb + (st) * STAGE2;                                \
    _Pragma("unroll")                                                  \
    for (int i = 0; i < 6; i++)                                        \
        CP_ASYNC16(base + doff[i], gsrc[i] + (k0));                    \
} while (0)

#pragma unroll
    for (int s = 0; s < N2ST - 1; s++) {
        LOAD_STG(s, s * G2BK);
        CP_COMMIT();
    }

    const uint32_t aoff = (wm * 64 + (lane & 15)) * ROWB2 + ((lane >> 4) << 4);
    const uint32_t boff = (wn * 64 + (lane & 15)) * ROWB2 + ((lane >> 4) << 4);

#pragma unroll 1
    for (int c = 0; c < N2CH; c++) {
        const int st = c & (N2ST - 1);
        CP_WAIT(2);
        __syncthreads();
        if (c + N2ST - 1 < N2CH) LOAD_STG((c + N2ST - 1) & (N2ST - 1), (c + N2ST - 1) * G2BK);
        CP_COMMIT();

        const uint32_t ab = sb + st * STAGE2;
        const uint32_t bb = ab + ATILE2;

#pragma unroll
        for (int ks = 0; ks < 2; ks++) {
            uint32_t a[4][4];
            uint32_t bfr[8][2];
#pragma unroll
            for (int mi = 0; mi < 4; mi++)
                LDM_X4(a[mi][0], a[mi][1], a[mi][2], a[mi][3],
                       ab + aoff + mi * (16 * ROWB2) + ks * 32);
#pragma unroll
            for (int j = 0; j < 4; j++) {
                uint32_t r0, r1, r2, r3;
                LDM_X4(r0, r1, r2, r3, bb + boff + j * (16 * ROWB2) + ks * 32);
                bfr[2*j][0]   = r0; bfr[2*j][1]   = r2;
                bfr[2*j+1][0] = r1; bfr[2*j+1][1] = r3;
            }
#pragma unroll
            for (int mi = 0; mi < 4; mi++)
#pragma unroll
                for (int ni = 0; ni < 8; ni++)
                    MMA16816(acc[mi][ni], a[mi], bfr[ni]);
        }
    }
#undef LOAD_STG

    if (MODE == 0) {
        // plain fp32 + bias
#pragma unroll
        for (int mi = 0; mi < 4; mi++) {
            int ra = m0 + wm * 64 + mi * 16 + (lane >> 2);
#pragma unroll
            for (int ni = 0; ni < 8; ni++) {
                int c0 = n0 + wn * 64 + ni * 8 + (lane & 3) * 2;
                float2 bb2 = *(const float2*)(bq + c0);
                float2 o0 = make_float2(acc[mi][ni][0] + bb2.x, acc[mi][ni][1] + bb2.y);
                float2 o1 = make_float2(acc[mi][ni][2] + bb2.x, acc[mi][ni][3] + bb2.y);
                *(float2*)(C + (size_t)ra * N + c0)       = o0;
                *(float2*)(C + (size_t)(ra + 8) * N + c0) = o1;
            }
        }
    } else {
        // fused QKV epilogue: route by n0 segment; rope for q/k; split hi/lo
        const int spv = spos[0];
        int seg, cbase;
        if (n0 < DD)            { seg = 0; cbase = 0; }
        else if (n0 < DD + KVD) { seg = 1; cbase = DD; }
        else                    { seg = 2; cbase = DD + KVD; }
        const float* bias = (seg == 0) ? bq : (seg == 1 ? bk : bv);
        __nv_bfloat16* dh = (seg == 0) ? qh : (seg == 1 ? kh : vh);
        __nv_bfloat16* dl = (seg == 0) ? ql : (seg == 1 ? kl : vl);
        const int   ldd = (seg == 0) ? DD : KVD;
        const float sc  = (seg == 0) ? QSCALE : 1.0f;

#pragma unroll
        for (int mi = 0; mi < 4; mi++) {
            int ra = m0 + wm * 64 + mi * 16 + (lane >> 2);
            int rb = ra + 8;
            int sa = ra & (SS - 1);
            int sbt = rb & (SS - 1);
#pragma unroll
            for (int ni = 0; ni < 8; ni++) {
                int c  = n0 + wn * 64 + ni * 8 + (lane & 3) * 2;
                int cl = c - cbase;
                float b0 = bias[cl], b1 = bias[cl + 1];
                float v0 = acc[mi][ni][0] + b0, v1 = acc[mi][ni][1] + b1;
                float v2 = acc[mi][ni][2] + b0, v3 = acc[mi][ni][3] + b1;
                if (seg < 2) {
                    int p = (c & 127) >> 1;
                    float2 fa = *(const float2*)(fc + ((size_t)(spv + sa)  * 64 + p) * 2);
                    float2 fb = *(const float2*)(fc + ((size_t)(spv + sbt) * 64 + p) * 2);
                    float o0 = (v0 * fa.x - v1 * fa.y) * sc;
                    float o1 = (v0 * fa.y + v1 * fa.x) * sc;
                    float o2 = (v2 * fb.x - v3 * fb.y) * sc;
                    float o3 = (v2 * fb.y + v3 * fb.x) * sc;
                    v0 = o0; v1 = o1; v2 = o2; v3 = o3;
                }
                uint32_t h0 = pack_bf16(v0, v1);
                uint32_t h1 = pack_bf16(v2, v3);
                float f0 = __uint_as_float(h0 << 16), f1 = __uint_as_float(h0 & 0xffff0000u);
                float f2 = __uint_as_float(h1 << 16), f3 = __uint_as_float(h1 & 0xffff0000u);
                uint32_t l0 = pack_bf16(v0 - f0, v1 - f1);
                uint32_t l1 = pack_bf16(v2 - f2, v3 - f3);
                *(uint32_t*)(dh + (size_t)ra * ldd + cl) = h0;
                *(uint32_t*)(dl + (size_t)ra * ldd + cl) = l0;
                *(uint32_t*)(dh + (size_t)rb * ldd + cl) = h1;
                *(uint32_t*)(dl + (size_t)rb * ldd + cl) = l1;
            }
        }
    }
}

// ---------------------------------------------------------------------------
// Tensor-core causal flash attention (R4, unchanged)
// ---------------------------------------------------------------------------
#define AROW     272
#define SQ_SZ    (128 * AROW)
#define KT_SZ    (64 * AROW)
#define STG_KH   0
#define STG_KL   17408
#define STG_VH   34816
#define STG_VL   52224
#define STG_SZ   (4 * KT_SZ)
#define ATT_SMEM (2 * SQ_SZ + 2 * STG_SZ)

__device__ __forceinline__ void att_load_kv(
    uint32_t dst, const __nv_bfloat16* khb, const __nv_bfloat16* klb,
    const __nv_bfloat16* vhb, const __nv_bfloat16* vlb, int n0, int t)
{
#pragma unroll
    for (int i = 0; i < 4; ++i) {
        int id = t + i * 256;
        int r  = id >> 4, c = id & 15;
        uint32_t o  = r * AROW + c * 16;
        size_t   go = (size_t)(n0 + r) * (KVH*HD) + c * 8;
        CP_ASYNC16(dst + STG_KH + o, khb + go);
        CP_ASYNC16(dst + STG_KL + o, klb + go);
        CP_ASYNC16(dst + STG_VH + o, vhb + go);
        CP_ASYNC16(dst + STG_VL + o, vlb + go);
    }
}

__global__ __launch_bounds__(256, 1) void attn_mma(
    const __nv_bfloat16* __restrict__ qh, const __nv_bfloat16* __restrict__ ql,
    const __nv_bfloat16* __restrict__ kh, const __nv_bfloat16* __restrict__ kl,
    const __nv_bfloat16* __restrict__ vh, const __nv_bfloat16* __restrict__ vl,
    __nv_bfloat16* __restrict__ cc)
{
    extern __shared__ char sm[];
    const int b   = blockIdx.z;
    const int h   = blockIdx.y;
    const int mb  = gridDim.x - 1 - blockIdx.x;
    const int m0  = mb * 128;
    const int kvh = h / GROUP;
    const int t    = threadIdx.x;
    const int lane = t & 31;
    const int w    = t >> 5;

    const uint32_t sb   = smem_u32(sm);
    const uint32_t sQh  = sb;
    const uint32_t sQl  = sb + SQ_SZ;
    const uint32_t sStg = sb + 2 * SQ_SZ;

    const __nv_bfloat16* qhb = qh + ((size_t)(b*SS + m0) * QH + h) * HD;
    const __nv_bfloat16* qlb = ql + ((size_t)(b*SS + m0) * QH + h) * HD;
    const __nv_bfloat16* khb = kh + ((size_t)b*SS*KVH + kvh) * HD;
    const __nv_bfloat16* klb = kl + ((size_t)b*SS*KVH + kvh) * HD;
    const __nv_bfloat16* vhb = vh + ((size_t)b*SS*KVH + kvh) * HD;
    const __nv_bfloat16* vlb = vl + ((size_t)b*SS*KVH + kvh) * HD;

#pragma unroll
    for (int i = 0; i < 8; ++i) {
        int id = t + i * 256;
        int r  = id >> 4, c = id & 15;
        uint32_t o  = r * AROW + c * 16;
        size_t   go = (size_t)r * (QH*HD) + c * 8;
        CP_ASYNC16(sQh + o, qhb + go);
        CP_ASYNC16(sQl + o, qlb + go);
    }
    att_load_kv(sStg, khb, klb, vhb, vlb, 0, t);
    CP_COMMIT();
    const int ntiles = 2 * mb + 2;
    if (ntiles > 1) att_load_kv(sStg + STG_SZ, khb, klb, vhb, vlb, 64, t);
    CP_COMMIT();

    const uint32_t qoff = (w * 16 + (lane & 15)) * AROW + ((lane >> 4) << 4);
    const uint32_t koff = (lane & 15) * AROW + ((lane >> 4) << 4);
    const int vrow = (lane & 7) + ((lane >> 4) << 3);
    const uint32_t vcol = ((lane >> 3) & 1) << 4;

    float O[16][4];
#pragma unroll
    for (int i = 0; i < 16; i++)
#pragma unroll
        for (int j = 0; j < 4; j++) O[i][j] = 0.f;
    float mx0 = -INFINITY, mx1 = -INFINITY, l0 = 0.f, l1 = 0.f;

    const int row0 = m0 + w * 16 + (lane >> 2);
    const int row1 = row0 + 8;
    const int wrow_hi = m0 + w * 16 + 15;
    const int wrow_lo = m0 + w * 16;

    for (int it = 0; it < ntiles; ++it) {
        const int n0 = it * 64;
        CP_WAIT(1);
        __syncthreads();
        const uint32_t stg = sStg + (it & 1) * STG_SZ;

        if (n0 <= wrow_hi) {
            float S[8][4];
#pragma unroll
            for (int i = 0; i < 8; i++)
#pragma unroll
                for (int j = 0; j < 4; j++) S[i][j] = 0.f;

#pragma unroll
            for (int ch = 0; ch < 8; ++ch) {
                uint32_t aq[4], al[4];
                LDM_X4(aq[0], aq[1], aq[2], aq[3], sQh + qoff + ch * 32);
                LDM_X4(al[0], al[1], al[2], al[3], sQl + qoff + ch * 32);
#pragma unroll
                for (int p = 0; p < 4; ++p) {
                    uint32_t h0,h1,h2,h3, e0,e1,e2,e3;
                    LDM_X4(h0,h1,h2,h3, stg + STG_KH + koff + p*(16*AROW) + ch*32);
                    LDM_X4(e0,e1,e2,e3, stg + STG_KL + koff + p*(16*AROW) + ch*32);
                    uint32_t bh0[2] = {h0, h2}, bh1[2] = {h1, h3};
                    uint32_t bl0[2] = {e0, e2}, bl1[2] = {e1, e3};
                    MMA16816(S[2*p],   aq, bh0);
                    MMA16816(S[2*p+1], aq, bh1);
                    MMA16816(S[2*p],   al, bh0);
                    MMA16816(S[2*p+1], al, bh1);
                    MMA16816(S[2*p],   aq, bl0);
                    MMA16816(S[2*p+1], aq, bl1);
                }
            }

            if (n0 + 63 > wrow_lo) {
#pragma unroll
                for (int p = 0; p < 8; ++p) {
                    int c = n0 + p * 8 + (lane & 3) * 2;
                    if (c     > row0) S[p][0] = -INFINITY;
                    if (c + 1 > row0) S[p][1] = -INFINITY;
                    if (c     > row1) S[p][2] = -INFINITY;
                    if (c + 1 > row1) S[p][3] = -INFINITY;
                }
            }

            float t0 = -INFINITY, t1 = -INFINITY;
#pragma unroll
            for (int p = 0; p < 8; ++p) {
                t0 = fmaxf(t0, fmaxf(S[p][0], S[p][1]));
                t1 = fmaxf(t1, fmaxf(S[p][2], S[p][3]));
            }
            t0 = fmaxf(t0, __shfl_xor_sync(0xffffffffu, t0, 1));
            t0 = fmaxf(t0, __shfl_xor_sync(0xffffffffu, t0, 2));
            t1 = fmaxf(t1, __shfl_xor_sync(0xffffffffu, t1, 1));
            t1 = fmaxf(t1, __shfl_xor_sync(0xffffffffu, t1, 2));
            float mn0 = fmaxf(mx0, t0), mn1 = fmaxf(mx1, t1);
            float cr0 = ex2f(mx0 - mn0), cr1 = ex2f(mx1 - mn1);
            mx0 = mn0; mx1 = mn1;

            float sa0 = 0.f, sa1 = 0.f;
#pragma unroll
            for (int p = 0; p < 8; ++p) {
                S[p][0] = ex2f(S[p][0] - mn0);
                S[p][1] = ex2f(S[p][1] - mn0);
                S[p][2] = ex2f(S[p][2] - mn1);
                S[p][3] = ex2f(S[p][3] - mn1);
                sa0 += S[p][0] + S[p][1];
                sa1 += S[p][2] + S[p][3];
            }
            sa0 += __shfl_xor_sync(0xffffffffu, sa0, 1);
            sa0 += __shfl_xor_sync(0xffffffffu, sa0, 2);
            sa1 += __shfl_xor_sync(0xffffffffu, sa1, 1);
            sa1 += __shfl_xor_sync(0xffffffffu, sa1, 2);
            l0 = l0 * cr0 + sa0;
            l1 = l1 * cr1 + sa1;

#pragma unroll
            for (int i = 0; i < 16; i++) {
                O[i][0] *= cr0; O[i][1] *= cr0;
                O[i][2] *= cr1; O[i][3] *= cr1;
            }

#pragma unroll
            for (int jc = 0; jc < 4; ++jc) {
                uint32_t ph[4], pl[4];
#pragma unroll
                for (int q2 = 0; q2 < 2; ++q2) {
                    float p0 = S[2*jc + q2][0], p1 = S[2*jc + q2][1];
                    float p2 = S[2*jc + q2][2], p3 = S[2*jc + q2][3];
                    uint32_t hp0 = pack_bf16(p0, p1);
                    uint32_t hp1 = pack_bf16(p2, p3);
                    float f0 = __uint_as_float(hp0 << 16);
                    float f1 = __uint_as_float(hp0 & 0xffff0000u);
                    float f2 = __uint_as_float(hp1 << 16);
                    float f3 = __uint_as_float(hp1 & 0xffff0000u);
                    ph[2*q2]   = hp0;  ph[2*q2+1] = hp1;
                    pl[2*q2]   = pack_bf16(p0 - f0, p1 - f1);
                    pl[2*q2+1] = pack_bf16(p2 - f2, p3 - f3);
                }
                const uint32_t vro = (jc * 16 + vrow) * AROW + vcol;
#pragma unroll
                for (int db = 0; db < 8; ++db) {
                    uint32_t a0,a1,a2,a3, c0,c1,c2,c3;
                    LDM_X4T(a0,a1,a2,a3, stg + STG_VH + vro + db * 32);
                    LDM_X4T(c0,c1,c2,c3, stg + STG_VL + vro + db * 32);
                    uint32_t bh0[2] = {a0, a2}, bh1[2] = {a1, a3};
                    uint32_t bl0[2] = {c0, c2}, bl1[2] = {c1, c3};
                    MMA16816(O[2*db],   ph, bh0);
                    MMA16816(O[2*db+1], ph, bh1);
                    MMA16816(O[2*db],   pl, bh0);
                    MMA16816(O[2*db+1], pl, bh1);
                    MMA16816(O[2*db],   ph, bl0);
                    MMA16816(O[2*db+1], ph, bl1);
                }
            }
        }

        __syncthreads();
        if (it + 2 < ntiles)
            att_load_kv(sStg + (it & 1) * STG_SZ, khb, klb, vhb, vlb, n0 + 128, t);
        CP_COMMIT();
    }

    float inv0 = 1.0f / l0, inv1 = 1.0f / l1;
    const size_t base0 = (size_t)(b * SS + row0) * K3;
    const size_t base1 = (size_t)(b * SS + row1) * K3;
    const int colb = h * 128 + (lane & 3) * 2;
#pragma unroll
    for (int dt = 0; dt < 16; ++dt) {
        int col = colb + dt * 8;
        float v0 = O[dt][0] * inv0, v1 = O[dt][1] * inv0;
        float v2 = O[dt][2] * inv1, v3 = O[dt][3] * inv1;
        uint32_t hi0 = pack_bf16(v0, v1);
        uint32_t hi1 = pack_bf16(v2, v3);
        float f0 = __uint_as_float(hi0 << 16), f1 = __uint_as_float(hi0 & 0xffff0000u);
        float f2 = __uint_as_float(hi1 << 16), f3 = __uint_as_float(hi1 & 0xffff0000u);
        uint32_t lo0 = pack_bf16(v0 - f0, v1 - f1);
        uint32_t lo1 = pack_bf16(v2 - f2, v3 - f3);
        *(uint32_t*)(cc + base0 + col)        = hi0;
        *(uint32_t*)(cc + base0 + DD + col)   = lo0;
        *(uint32_t*)(cc + base0 + 2*DD + col) = hi0;
        *(uint32_t*)(cc + base1 + col)        = hi1;
        *(uint32_t*)(cc + base1 + DD + col)   = lo1;
        *(uint32_t*)(cc + base1 + 2*DD + col) = hi1;
    }
}

// ---------------------------------------------------------------------------
// launch
// ---------------------------------------------------------------------------
extern "C" void kernel_launch(void* const* d_in, const int* in_sizes, int n_in,
                              void* d_out, int out_size)
{
    const float* xs   = (const float*)d_in[0];
    const int*   spos = (const int*)  d_in[1];
    const float* fc   = (const float*)d_in[2];
    const float* Wq   = (const float*)d_in[3];
    const float* bq   = (const float*)d_in[4];
    const float* Wk   = (const float*)d_in[5];
    const float* bk   = (const float*)d_in[6];
    const float* Wv   = (const float*)d_in[7];
    const float* bv   = (const float*)d_in[8];
    const float* Wo   = (const float*)d_in[9];
    const float* bo   = (const float*)d_in[10];
    float* out = (float*)d_out;

    __nv_bfloat16 *xc, *wqkv, *woc, *cc;
    __nv_bfloat16 *qhp, *qlp, *khp, *klp, *vhp, *vlp;
    cudaGetSymbolAddress((void**)&xc,   g_xc);
    cudaGetSymbolAddress((void**)&wqkv, g_wqkv);
    cudaGetSymbolAddress((void**)&woc,  g_woc);
    cudaGetSymbolAddress((void**)&cc,   g_cc);
    cudaGetSymbolAddress((void**)&qhp,  g_qh);
    cudaGetSymbolAddress((void**)&qlp,  g_ql);
    cudaGetSymbolAddress((void**)&khp,  g_kh);
    cudaGetSymbolAddress((void**)&klp,  g_kl);
    cudaGetSymbolAddress((void**)&vhp,  g_vh);
    cudaGetSymbolAddress((void**)&vlp,  g_vl);

    cudaFuncSetAttribute(gemm_big<0>, cudaFuncAttributeMaxDynamicSharedMemorySize, GSMEM2);
    cudaFuncSetAttribute(gemm_big<1>, cudaFuncAttributeMaxDynamicSharedMemorySize, GSMEM2);
    cudaFuncSetAttribute(attn_mma,    cudaFuncAttributeMaxDynamicSharedMemorySize, ATT_SMEM);

    // splits (launches 1-5)
    {
        int n;
        n = TOK*DD/4;  split_bf16_kernel<<<(n+255)/256, 256>>>(xs, xc, DD, n, 0);
        n = DD*DD/4;   split_bf16_kernel<<<(n+255)/256, 256>>>(Wq, wqkv, DD, n, 1);
        n = KVD*DD/4;  split_bf16_kernel<<<(n+255)/256, 256>>>(Wk, wqkv + (size_t)DD*K3, DD, n, 1);
        n = KVD*DD/4;  split_bf16_kernel<<<(n+255)/256, 256>>>(Wv, wqkv + (size_t)(DD+KVD)*K3, DD, n, 1);
        n = DD*DD/4;   split_bf16_kernel<<<(n+255)/256, 256>>>(Wo, woc, DD, n, 1);
    }

    // fused QKV projection + rope + split  (launch 6 — profiled slot)
    gemm_big<1><<<dim3(TOK/CT2M, NQKV/CT2N), 256, GSMEM2>>>(
        xc, wqkv, bq, bk, bv, nullptr, 0, fc, spos,
        qhp, qlp, khp, klp, vhp, vlp);

    // attention (launch 7)
    attn_mma<<<dim3(SS/128, QH, BB), 256, ATT_SMEM>>>(qhp, qlp, khp, klp, vhp, vlp, cc);

    // output projection (launch 8)
    gemm_big<0><<<dim3(TOK/CT2M, DD/CT2N), 256, GSMEM2>>>(
        cc, woc, bo, nullptr, nullptr, out, DD, nullptr, nullptr,
        nullptr, nullptr, nullptr, nullptr, nullptr, nullptr);
}

// round 6
// speedup vs baseline: 1.1612x; 1.1612x over previous
#include <cuda_runtime.h>
#include <cuda_bf16.h>
#include <math.h>
#include <stdint.h>

// Problem constants
#define BB   2
#define SS   2048
#define DD   4096
#define QH   32
#define KVH  8
#define HD   128
#define KVD  (KVH*HD)      // 1024
#define GROUP (QH/KVH)     // 4
#define TOK  (BB*SS)       // 4096
#define K3   (3*DD)        // 12288
#define NQKV (DD + 2*KVD)  // 6144

#define QSCALE (0.08838834764831845f * 1.4426950408889634f)

// ---------------------------------------------------------------------------
// Scratch
// ---------------------------------------------------------------------------
__device__ __align__(16) __nv_bfloat16 g_xc  [TOK*K3];
__device__ __align__(16) __nv_bfloat16 g_wqkv[(size_t)NQKV*K3];
__device__ __align__(16) __nv_bfloat16 g_woc [DD*K3];
__device__ __align__(16) __nv_bfloat16 g_cc  [TOK*K3];

__device__ __align__(16) __nv_bfloat16 g_qh[TOK*DD];
__device__ __align__(16) __nv_bfloat16 g_ql[TOK*DD];
__device__ __align__(16) __nv_bfloat16 g_kh[TOK*KVD];
__device__ __align__(16) __nv_bfloat16 g_kl[TOK*KVD];
__device__ __align__(16) __nv_bfloat16 g_vh[TOK*KVD];
__device__ __align__(16) __nv_bfloat16 g_vl[TOK*KVD];

// ---------------------------------------------------------------------------
// helpers
// ---------------------------------------------------------------------------
__device__ __forceinline__ uint32_t smem_u32(const void* p) {
    uint32_t a;
    asm("{ .reg .u64 t; cvta.to.shared.u64 t, %1; cvt.u32.u64 %0, t; }" : "=r"(a) : "l"(p));
    return a;
}

#define CP_ASYNC16(dst, src) \
    asm volatile("cp.async.cg.shared.global [%0], [%1], 16;" :: "r"(dst), "l"(src))
#define CP_COMMIT()   asm volatile("cp.async.commit_group;" ::: "memory")
#define CP_WAIT(n)    asm volatile("cp.async.wait_group %0;" :: "n"(n) : "memory")

#define LDM_X4(r0, r1, r2, r3, addr) \
    asm volatile("ldmatrix.sync.aligned.m8n8.x4.shared.b16 {%0,%1,%2,%3}, [%4];" \
        : "=r"(r0), "=r"(r1), "=r"(r2), "=r"(r3) : "r"(addr))

#define LDM_X4T(r0, r1, r2, r3, addr) \
    asm volatile("ldmatrix.sync.aligned.m8n8.x4.trans.shared.b16 {%0,%1,%2,%3}, [%4];" \
        : "=r"(r0), "=r"(r1), "=r"(r2), "=r"(r3) : "r"(addr))

#define MMA16816(d, a, b) \
    asm volatile("mma.sync.aligned.m16n8k16.row.col.f32.bf16.bf16.f32 " \
        "{%0,%1,%2,%3},{%4,%5,%6,%7},{%8,%9},{%0,%1,%2,%3};" \
        : "+f"((d)[0]), "+f"((d)[1]), "+f"((d)[2]), "+f"((d)[3]) \
        : "r"((a)[0]), "r"((a)[1]), "r"((a)[2]), "r"((a)[3]), \
          "r"((b)[0]), "r"((b)[1]))

__device__ __forceinline__ uint32_t pack_bf16(float a, float b) {
    uint32_t d;
    asm("cvt.rn.bf16x2.f32 %0, %1, %2;" : "=r"(d) : "f"(b), "f"(a));
    return d;
}
__device__ __forceinline__ float ex2f(float x) {
    float r; asm("ex2.approx.f32 %0, %1;" : "=f"(r) : "f"(x)); return r;
}

// ---------------------------------------------------------------------------
// fp32 -> 3-term bf16 split (concatenated K)
// mode 0 (A-form): [hi | lo | hi]   mode 1 (B-form): [hi | hi | lo]
// ---------------------------------------------------------------------------
__global__ void split_bf16_kernel(const float* __restrict__ in,
                                  __nv_bfloat16* __restrict__ out,
                                  int K, int total4, int mode)
{
    int idx = blockIdx.x * blockDim.x + threadIdx.x;
    if (idx >= total4) return;
    float4 v = ((const float4*)in)[idx];
    int K4 = K >> 2;
    int r  = idx / K4;
    int k  = (idx - r * K4) << 2;
    float vv[4] = {v.x, v.y, v.z, v.w};
    __nv_bfloat16 h[4], l[4];
#pragma unroll
    for (int i = 0; i < 4; i++) {
        h[i] = __float2bfloat16(vv[i]);
        l[i] = __float2bfloat16(vv[i] - __bfloat162float(h[i]));
    }
    __nv_bfloat16* row = out + (size_t)r * (3*K);
    if (mode == 0) {
        *(uint2*)(row + k)       = *(uint2*)h;
        *(uint2*)(row + K + k)   = *(uint2*)l;
        *(uint2*)(row + 2*K + k) = *(uint2*)h;
    } else {
        *(uint2*)(row + k)       = *(uint2*)h;
        *(uint2*)(row + K + k)   = *(uint2*)h;
        *(uint2*)(row + 2*K + k) = *(uint2*)l;
    }
}

// ---------------------------------------------------------------------------
// bf16 MMA GEMM: C = A[M,K3] @ B[N,K3]^T  (R4-proven geometry)
// CTA 128x128, BK=32, 256 threads (8 warps, 2m x 4n of 64x32), 4 stages, occ 2.
// MODE 0: fp32 C = acc + bias (bias in bq)
// MODE 1: fused QKV epilogue: route by column segment, rope q/k, hi/lo split.
// ---------------------------------------------------------------------------
#define CTM   128
#define CTN   128
#define GBK   32
#define NST   4
#define NCH   (K3 / GBK)
#define ROWB  80
#define ATILE (CTM * ROWB)
#define BTILE (CTN * ROWB)
#define STAGE (ATILE + BTILE)
#define GSMEM (NST * STAGE)

template<int MODE>
__global__ __launch_bounds__(256, 2) void gemm_mma(
    const __nv_bfloat16* __restrict__ A, const __nv_bfloat16* __restrict__ B,
    const float* __restrict__ bq, const float* __restrict__ bk,
    const float* __restrict__ bv,
    float* __restrict__ C, int N,
    const float* __restrict__ fc, const int* __restrict__ spos,
    __nv_bfloat16* __restrict__ qh, __nv_bfloat16* __restrict__ ql,
    __nv_bfloat16* __restrict__ kh, __nv_bfloat16* __restrict__ kl,
    __nv_bfloat16* __restrict__ vh, __nv_bfloat16* __restrict__ vl)
{
    extern __shared__ char smraw[];
    const int t    = threadIdx.x;
    const int lane = t & 31;
    const int wid  = t >> 5;
    const int wm   = wid & 1;
    const int wn   = wid >> 1;
    const int m0   = blockIdx.x * CTM;
    const int n0   = blockIdx.y * CTN;
    const uint32_t sb = smem_u32(smraw);

    float acc[4][4][4];
#pragma unroll
    for (int i = 0; i < 4; i++)
#pragma unroll
        for (int j = 0; j < 4; j++)
#pragma unroll
            for (int r = 0; r < 4; r++) acc[i][j][r] = 0.f;

    const __nv_bfloat16* Ag0 = A + (size_t)(m0 + (t >> 2)) * K3 + (t & 3) * 8;
    const __nv_bfloat16* Ag1 = A + (size_t)(m0 + ((t + 256) >> 2)) * K3 + (t & 3) * 8;
    const __nv_bfloat16* Bg0 = B + (size_t)(n0 + (t >> 2)) * K3 + (t & 3) * 8;
    const __nv_bfloat16* Bg1 = B + (size_t)(n0 + ((t + 256) >> 2)) * K3 + (t & 3) * 8;
    const uint32_t sA0 = (t >> 2) * ROWB + (t & 3) * 16;
    const uint32_t sA1 = ((t + 256) >> 2) * ROWB + (t & 3) * 16;

#define LOAD_STAGE(st, k0) do {                                        \
    uint32_t ab = sb + (st) * STAGE;                                   \
    uint32_t bb = ab + ATILE;                                          \
    CP_ASYNC16(ab + sA0, Ag0 + (k0));                                  \
    CP_ASYNC16(ab + sA1, Ag1 + (k0));                                  \
    CP_ASYNC16(bb + sA0, Bg0 + (k0));                                  \
    CP_ASYNC16(bb + sA1, Bg1 + (k0));                                  \
} while (0)

#pragma unroll
    for (int s = 0; s < NST - 1; s++) {
        LOAD_STAGE(s, s * GBK);
        CP_COMMIT();
    }

    const uint32_t aoffs = (wm * 64 + (lane & 15)) * ROWB + ((lane >> 4) << 4);
    const uint32_t boffs = (wn * 32 + (lane & 15)) * ROWB + ((lane >> 4) << 4);

    for (int c = 0; c < NCH; c++) {
        const int st = c & (NST - 1);
        CP_WAIT(2);
        __syncthreads();
        if (c + NST - 1 < NCH) LOAD_STAGE((c + NST - 1) & (NST - 1), (c + NST - 1) * GBK);
        CP_COMMIT();

        const uint32_t ab = sb + st * STAGE;
        const uint32_t bb = ab + ATILE;

#pragma unroll
        for (int ks = 0; ks < 2; ks++) {
            uint32_t a[4][4];
            uint32_t bf[4][2];
#pragma unroll
            for (int mi = 0; mi < 4; mi++)
                LDM_X4(a[mi][0], a[mi][1], a[mi][2], a[mi][3],
                       ab + aoffs + mi * 16 * ROWB + ks * 32);
#pragma unroll
            for (int p = 0; p < 2; p++) {
                uint32_t r0, r1, r2, r3;
                LDM_X4(r0, r1, r2, r3, bb + boffs + p * 16 * ROWB + ks * 32);
                bf[2*p][0]   = r0; bf[2*p][1]   = r2;
                bf[2*p+1][0] = r1; bf[2*p+1][1] = r3;
            }
#pragma unroll
            for (int mi = 0; mi < 4; mi++)
#pragma unroll
                for (int ni = 0; ni < 4; ni++)
                    MMA16816(acc[mi][ni], a[mi], bf[ni]);
        }
    }
#undef LOAD_STAGE

    if (MODE == 0) {
#pragma unroll
        for (int mi = 0; mi < 4; mi++) {
            int r0 = m0 + wm * 64 + mi * 16 + (lane >> 2);
#pragma unroll
            for (int ni = 0; ni < 4; ni++) {
                int col = n0 + wn * 32 + ni * 8 + (lane & 3) * 2;
                float2 bv2 = *(const float2*)(bq + col);
                float2 o0 = make_float2(acc[mi][ni][0] + bv2.x, acc[mi][ni][1] + bv2.y);
                float2 o1 = make_float2(acc[mi][ni][2] + bv2.x, acc[mi][ni][3] + bv2.y);
                *(float2*)(C + (size_t)r0 * N + col)       = o0;
                *(float2*)(C + (size_t)(r0 + 8) * N + col) = o1;
            }
        }
    } else {
        // fused QKV epilogue: this CTA's 128-col tile lies in one segment
        const int spv = spos[0];
        int seg, cbase;
        if (n0 < DD)            { seg = 0; cbase = 0; }
        else if (n0 < DD + KVD) { seg = 1; cbase = DD; }
        else                    { seg = 2; cbase = DD + KVD; }
        const float* bias = (seg == 0) ? bq : (seg == 1 ? bk : bv);
        __nv_bfloat16* dh = (seg == 0) ? qh : (seg == 1 ? kh : vh);
        __nv_bfloat16* dl = (seg == 0) ? ql : (seg == 1 ? kl : vl);
        const int   ldd = (seg == 0) ? DD : KVD;
        const float sc  = (seg == 0) ? QSCALE : 1.0f;

#pragma unroll
        for (int mi = 0; mi < 4; mi++) {
            int ra = m0 + wm * 64 + mi * 16 + (lane >> 2);
            int rb = ra + 8;
            int sa  = ra & (SS - 1);
            int sbt = rb & (SS - 1);
#pragma unroll
            for (int ni = 0; ni < 4; ni++) {
                int c  = n0 + wn * 32 + ni * 8 + (lane & 3) * 2;
                int cl = c - cbase;
                float b0 = bias[cl], b1 = bias[cl + 1];
                float v0 = acc[mi][ni][0] + b0, v1 = acc[mi][ni][1] + b1;
                float v2 = acc[mi][ni][2] + b0, v3 = acc[mi][ni][3] + b1;
                if (seg < 2) {
                    int p = (c & 127) >> 1;
                    float2 fa = *(const float2*)(fc + ((size_t)(spv + sa)  * 64 + p) * 2);
                    float2 fb = *(const float2*)(fc + ((size_t)(spv + sbt) * 64 + p) * 2);
                    float o0 = (v0 * fa.x - v1 * fa.y) * sc;
                    float o1 = (v0 * fa.y + v1 * fa.x) * sc;
                    float o2 = (v2 * fb.x - v3 * fb.y) * sc;
                    float o3 = (v2 * fb.y + v3 * fb.x) * sc;
                    v0 = o0; v1 = o1; v2 = o2; v3 = o3;
                }
                uint32_t h0 = pack_bf16(v0, v1);
                uint32_t h1 = pack_bf16(v2, v3);
                float f0 = __uint_as_float(h0 << 16), f1 = __uint_as_float(h0 & 0xffff0000u);
                float f2 = __uint_as_float(h1 << 16), f3 = __uint_as_float(h1 & 0xffff0000u);
                uint32_t l0 = pack_bf16(v0 - f0, v1 - f1);
                uint32_t l1 = pack_bf16(v2 - f2, v3 - f3);
                *(uint32_t*)(dh + (size_t)ra * ldd + cl) = h0;
                *(uint32_t*)(dl + (size_t)ra * ldd + cl) = l0;
                *(uint32_t*)(dh + (size_t)rb * ldd + cl) = h1;
                *(uint32_t*)(dl + (size_t)rb * ldd + cl) = l1;
            }
        }
    }
}

// ---------------------------------------------------------------------------
// Tensor-core causal flash attention (R4, unchanged)
// ---------------------------------------------------------------------------
#define AROW     272
#define SQ_SZ    (128 * AROW)
#define KT_SZ    (64 * AROW)
#define STG_KH   0
#define STG_KL   17408
#define STG_VH   34816
#define STG_VL   52224
#define STG_SZ   (4 * KT_SZ)
#define ATT_SMEM (2 * SQ_SZ + 2 * STG_SZ)

__device__ __forceinline__ void att_load_kv(
    uint32_t dst, const __nv_bfloat16* khb, const __nv_bfloat16* klb,
    const __nv_bfloat16* vhb, const __nv_bfloat16* vlb, int n0, int t)
{
#pragma unroll
    for (int i = 0; i < 4; ++i) {
        int id = t + i * 256;
        int r  = id >> 4, c = id & 15;
        uint32_t o  = r * AROW + c * 16;
        size_t   go = (size_t)(n0 + r) * (KVH*HD) + c * 8;
        CP_ASYNC16(dst + STG_KH + o, khb + go);
        CP_ASYNC16(dst + STG_KL + o, klb + go);
        CP_ASYNC16(dst + STG_VH + o, vhb + go);
        CP_ASYNC16(dst + STG_VL + o, vlb + go);
    }
}

__global__ __launch_bounds__(256, 1) void attn_mma(
    const __nv_bfloat16* __restrict__ qh, const __nv_bfloat16* __restrict__ ql,
    const __nv_bfloat16* __restrict__ kh, const __nv_bfloat16* __restrict__ kl,
    const __nv_bfloat16* __restrict__ vh, const __nv_bfloat16* __restrict__ vl,
    __nv_bfloat16* __restrict__ cc)
{
    extern __shared__ char sm[];
    const int b   = blockIdx.z;
    const int h   = blockIdx.y;
    const int mb  = gridDim.x - 1 - blockIdx.x;
    const int m0  = mb * 128;
    const int kvh = h / GROUP;
    const int t    = threadIdx.x;
    const int lane = t & 31;
    const int w    = t >> 5;

    const uint32_t sb   = smem_u32(sm);
    const uint32_t sQh  = sb;
    const uint32_t sQl  = sb + SQ_SZ;
    const uint32_t sStg = sb + 2 * SQ_SZ;

    const __nv_bfloat16* qhb = qh + ((size_t)(b*SS + m0) * QH + h) * HD;
    const __nv_bfloat16* qlb = ql + ((size_t)(b*SS + m0) * QH + h) * HD;
    const __nv_bfloat16* khb = kh + ((size_t)b*SS*KVH + kvh) * HD;
    const __nv_bfloat16* klb = kl + ((size_t)b*SS*KVH + kvh) * HD;
    const __nv_bfloat16* vhb = vh + ((size_t)b*SS*KVH + kvh) * HD;
    const __nv_bfloat16* vlb = vl + ((size_t)b*SS*KVH + kvh) * HD;

#pragma unroll
    for (int i = 0; i < 8; ++i) {
        int id = t + i * 256;
        int r  = id >> 4, c = id & 15;
        uint32_t o  = r * AROW + c * 16;
        size_t   go = (size_t)r * (QH*HD) + c * 8;
        CP_ASYNC16(sQh + o, qhb + go);
        CP_ASYNC16(sQl + o, qlb + go);
    }
    att_load_kv(sStg, khb, klb, vhb, vlb, 0, t);
    CP_COMMIT();
    const int ntiles = 2 * mb + 2;
    if (ntiles > 1) att_load_kv(sStg + STG_SZ, khb, klb, vhb, vlb, 64, t);
    CP_COMMIT();

    const uint32_t qoff = (w * 16 + (lane & 15)) * AROW + ((lane >> 4) << 4);
    const uint32_t koff = (lane & 15) * AROW + ((lane >> 4) << 4);
    const int vrow = (lane & 7) + ((lane >> 4) << 3);
    const uint32_t vcol = ((lane >> 3) & 1) << 4;

    float O[16][4];
#pragma unroll
    for (int i = 0; i < 16; i++)
#pragma unroll
        for (int j = 0; j < 4; j++) O[i][j] = 0.f;
    float mx0 = -INFINITY, mx1 = -INFINITY, l0 = 0.f, l1 = 0.f;

    const int row0 = m0 + w * 16 + (lane >> 2);
    const int row1 = row0 + 8;
    const int wrow_hi = m0 + w * 16 + 15;
    const int wrow_lo = m0 + w * 16;

    for (int it = 0; it < ntiles; ++it) {
        const int n0 = it * 64;
        CP_WAIT(1);
        __syncthreads();
        const uint32_t stg = sStg + (it & 1) * STG_SZ;

        if (n0 <= wrow_hi) {
            float S[8][4];
#pragma unroll
            for (int i = 0; i < 8; i++)
#pragma unroll
                for (int j = 0; j < 4; j++) S[i][j] = 0.f;

#pragma unroll
            for (int ch = 0; ch < 8; ++ch) {
                uint32_t aq[4], al[4];
                LDM_X4(aq[0], aq[1], aq[2], aq[3], sQh + qoff + ch * 32);
                LDM_X4(al[0], al[1], al[2], al[3], sQl + qoff + ch * 32);
#pragma unroll
                for (int p = 0; p < 4; ++p) {
                    uint32_t h0,h1,h2,h3, e0,e1,e2,e3;
                    LDM_X4(h0,h1,h2,h3, stg + STG_KH + koff + p*(16*AROW) + ch*32);
                    LDM_X4(e0,e1,e2,e3, stg + STG_KL + koff + p*(16*AROW) + ch*32);
                    uint32_t bh0[2] = {h0, h2}, bh1[2] = {h1, h3};
                    uint32_t bl0[2] = {e0, e2}, bl1[2] = {e1, e3};
                    MMA16816(S[2*p],   aq, bh0);
                    MMA16816(S[2*p+1], aq, bh1);
                    MMA16816(S[2*p],   al, bh0);
                    MMA16816(S[2*p+1], al, bh1);
                    MMA16816(S[2*p],   aq, bl0);
                    MMA16816(S[2*p+1], aq, bl1);
                }
            }

            if (n0 + 63 > wrow_lo) {
#pragma unroll
                for (int p = 0; p < 8; ++p) {
                    int c = n0 + p * 8 + (lane & 3) * 2;
                    if (c     > row0) S[p][0] = -INFINITY;
                    if (c + 1 > row0) S[p][1] = -INFINITY;
                    if (c     > row1) S[p][2] = -INFINITY;
                    if (c + 1 > row1) S[p][3] = -INFINITY;
                }
            }

            float t0 = -INFINITY, t1 = -INFINITY;
#pragma unroll
            for (int p = 0; p < 8; ++p) {
                t0 = fmaxf(t0, fmaxf(S[p][0], S[p][1]));
                t1 = fmaxf(t1, fmaxf(S[p][2], S[p][3]));
            }
            t0 = fmaxf(t0, __shfl_xor_sync(0xffffffffu, t0, 1));
            t0 = fmaxf(t0, __shfl_xor_sync(0xffffffffu, t0, 2));
            t1 = fmaxf(t1, __shfl_xor_sync(0xffffffffu, t1, 1));
            t1 = fmaxf(t1, __shfl_xor_sync(0xffffffffu, t1, 2));
            float mn0 = fmaxf(mx0, t0), mn1 = fmaxf(mx1, t1);
            float cr0 = ex2f(mx0 - mn0), cr1 = ex2f(mx1 - mn1);
            mx0 = mn0; mx1 = mn1;

            float sa0 = 0.f, sa1 = 0.f;
#pragma unroll
            for (int p = 0; p < 8; ++p) {
                S[p][0] = ex2f(S[p][0] - mn0);
                S[p][1] = ex2f(S[p][1] - mn0);
                S[p][2] = ex2f(S[p][2] - mn1);
                S[p][3] = ex2f(S[p][3] - mn1);
                sa0 += S[p][0] + S[p][1];
                sa1 += S[p][2] + S[p][3];
            }
            sa0 += __shfl_xor_sync(0xffffffffu, sa0, 1);
            sa0 += __shfl_xor_sync(0xffffffffu, sa0, 2);
            sa1 += __shfl_xor_sync(0xffffffffu, sa1, 1);
            sa1 += __shfl_xor_sync(0xffffffffu, sa1, 2);
            l0 = l0 * cr0 + sa0;
            l1 = l1 * cr1 + sa1;

#pragma unroll
            for (int i = 0; i < 16; i++) {
                O[i][0] *= cr0; O[i][1] *= cr0;
                O[i][2] *= cr1; O[i][3] *= cr1;
            }

#pragma unroll
            for (int jc = 0; jc < 4; ++jc) {
                uint32_t ph[4], pl[4];
#pragma unroll
                for (int q2 = 0; q2 < 2; ++q2) {
                    float p0 = S[2*jc + q2][0], p1 = S[2*jc + q2][1];
                    float p2 = S[2*jc + q2][2], p3 = S[2*jc + q2][3];
                    uint32_t hp0 = pack_bf16(p0, p1);
                    uint32_t hp1 = pack_bf16(p2, p3);
                    float f0 = __uint_as_float(hp0 << 16);
                    float f1 = __uint_as_float(hp0 & 0xffff0000u);
                    float f2 = __uint_as_float(hp1 << 16);
                    float f3 = __uint_as_float(hp1 & 0xffff0000u);
                    ph[2*q2]   = hp0;  ph[2*q2+1] = hp1;
                    pl[2*q2]   = pack_bf16(p0 - f0, p1 - f1);
                    pl[2*q2+1] = pack_bf16(p2 - f2, p3 - f3);
                }
                const uint32_t vro = (jc * 16 + vrow) * AROW + vcol;
#pragma unroll
                for (int db = 0; db < 8; ++db) {
                    uint32_t a0,a1,a2,a3, c0,c1,c2,c3;
                    LDM_X4T(a0,a1,a2,a3, stg + STG_VH + vro + db * 32);
                    LDM_X4T(c0,c1,c2,c3, stg + STG_VL + vro + db * 32);
                    uint32_t bh0[2] = {a0, a2}, bh1[2] = {a1, a3};
                    uint32_t bl0[2] = {c0, c2}, bl1[2] = {c1, c3};
                    MMA16816(O[2*db],   ph, bh0);
                    MMA16816(O[2*db+1], ph, bh1);
                    MMA16816(O[2*db],   pl, bh0);
                    MMA16816(O[2*db+1], pl, bh1);
                    MMA16816(O[2*db],   ph, bl0);
                    MMA16816(O[2*db+1], ph, bl1);
                }
            }
        }

        __syncthreads();
        if (it + 2 < ntiles)
            att_load_kv(sStg + (it & 1) * STG_SZ, khb, klb, vhb, vlb, n0 + 128, t);
        CP_COMMIT();
    }

    float inv0 = 1.0f / l0, inv1 = 1.0f / l1;
    const size_t base0 = (size_t)(b * SS + row0) * K3;
    const size_t base1 = (size_t)(b * SS + row1) * K3;
    const int colb = h * 128 + (lane & 3) * 2;
#pragma unroll
    for (int dt = 0; dt < 16; ++dt) {
        int col = colb + dt * 8;
        float v0 = O[dt][0] * inv0, v1 = O[dt][1] * inv0;
        float v2 = O[dt][2] * inv1, v3 = O[dt][3] * inv1;
        uint32_t hi0 = pack_bf16(v0, v1);
        uint32_t hi1 = pack_bf16(v2, v3);
        float f0 = __uint_as_float(hi0 << 16), f1 = __uint_as_float(hi0 & 0xffff0000u);
        float f2 = __uint_as_float(hi1 << 16), f3 = __uint_as_float(hi1 & 0xffff0000u);
        uint32_t lo0 = pack_bf16(v0 - f0, v1 - f1);
        uint32_t lo1 = pack_bf16(v2 - f2, v3 - f3);
        *(uint32_t*)(cc + base0 + col)        = hi0;
        *(uint32_t*)(cc + base0 + DD + col)   = lo0;
        *(uint32_t*)(cc + base0 + 2*DD + col) = hi0;
        *(uint32_t*)(cc + base1 + col)        = hi1;
        *(uint32_t*)(cc + base1 + DD + col)   = lo1;
        *(uint32_t*)(cc + base1 + 2*DD + col) = hi1;
    }
}

// ---------------------------------------------------------------------------
// launch
// ---------------------------------------------------------------------------
extern "C" void kernel_launch(void* const* d_in, const int* in_sizes, int n_in,
                              void* d_out, int out_size)
{
    const float* xs   = (const float*)d_in[0];
    const int*   spos = (const int*)  d_in[1];
    const float* fc   = (const float*)d_in[2];
    const float* Wq   = (const float*)d_in[3];
    const float* bq   = (const float*)d_in[4];
    const float* Wk   = (const float*)d_in[5];
    const float* bk   = (const float*)d_in[6];
    const float* Wv   = (const float*)d_in[7];
    const float* bv   = (const float*)d_in[8];
    const float* Wo   = (const float*)d_in[9];
    const float* bo   = (const float*)d_in[10];
    float* out = (float*)d_out;

    __nv_bfloat16 *xc, *wqkv, *woc, *cc;
    __nv_bfloat16 *qhp, *qlp, *khp, *klp, *vhp, *vlp;
    cudaGetSymbolAddress((void**)&xc,   g_xc);
    cudaGetSymbolAddress((void**)&wqkv, g_wqkv);
    cudaGetSymbolAddress((void**)&woc,  g_woc);
    cudaGetSymbolAddress((void**)&cc,   g_cc);
    cudaGetSymbolAddress((void**)&qhp,  g_qh);
    cudaGetSymbolAddress((void**)&qlp,  g_ql);
    cudaGetSymbolAddress((void**)&khp,  g_kh);
    cudaGetSymbolAddress((void**)&klp,  g_kl);
    cudaGetSymbolAddress((void**)&vhp,  g_vh);
    cudaGetSymbolAddress((void**)&vlp,  g_vl);

    cudaFuncSetAttribute(gemm_mma<0>, cudaFuncAttributeMaxDynamicSharedMemorySize, GSMEM);
    cudaFuncSetAttribute(gemm_mma<1>, cudaFuncAttributeMaxDynamicSharedMemorySize, GSMEM);
    cudaFuncSetAttribute(attn_mma,    cudaFuncAttributeMaxDynamicSharedMemorySize, ATT_SMEM);

    // splits (launches 1-5)
    {
        int n;
        n = TOK*DD/4;  split_bf16_kernel<<<(n+255)/256, 256>>>(xs, xc, DD, n, 0);
        n = DD*DD/4;   split_bf16_kernel<<<(n+255)/256, 256>>>(Wq, wqkv, DD, n, 1);
        n = KVD*DD/4;  split_bf16_kernel<<<(n+255)/256, 256>>>(Wk, wqkv + (size_t)DD*K3, DD, n, 1);
        n = KVD*DD/4;  split_bf16_kernel<<<(n+255)/256, 256>>>(Wv, wqkv + (size_t)(DD+KVD)*K3, DD, n, 1);
        n = DD*DD/4;   split_bf16_kernel<<<(n+255)/256, 256>>>(Wo, woc, DD, n, 1);
    }

    // fused QKV projection + rope + split (launch 6)
    gemm_mma<1><<<dim3(TOK/CTM, NQKV/CTN), 256, GSMEM>>>(
        xc, wqkv, bq, bk, bv, nullptr, 0, fc, spos,
        qhp, qlp, khp, klp, vhp, vlp);

    // attention (launch 7)
    attn_mma<<<dim3(SS/128, QH, BB), 256, ATT_SMEM>>>(qhp, qlp, khp, klp, vhp, vlp, cc);

    // output projection (launch 8)
    gemm_mma<0><<<dim3(TOK/CTM, DD/CTN), 256, GSMEM>>>(
        cc, woc, bo, nullptr, nullptr, out, DD, nullptr, nullptr,
        nullptr, nullptr, nullptr, nullptr, nullptr, nullptr);
}

// round 7
// speedup vs baseline: 1.2148x; 1.0461x over previous
#include <cuda_runtime.h>
#include <cuda_bf16.h>
#include <math.h>
#include <stdint.h>

// Problem constants
#define BB   2
#define SS   2048
#define DD   4096
#define QH   32
#define KVH  8
#define HD   128
#define KVD  (KVH*HD)      // 1024
#define GROUP (QH/KVH)     // 4
#define TOK  (BB*SS)       // 4096
#define K3   (3*DD)        // 12288
#define NQKV (DD + 2*KVD)  // 6144

#define QSCALE (0.08838834764831845f * 1.4426950408889634f)

// ---------------------------------------------------------------------------
// Scratch
// ---------------------------------------------------------------------------
__device__ __align__(16) __nv_bfloat16 g_xc  [TOK*K3];
__device__ __align__(16) __nv_bfloat16 g_wqkv[(size_t)NQKV*K3];
__device__ __align__(16) __nv_bfloat16 g_woc [DD*K3];
__device__ __align__(16) __nv_bfloat16 g_cc  [TOK*K3];

__device__ __align__(16) __nv_bfloat16 g_qh[TOK*DD];
__device__ __align__(16) __nv_bfloat16 g_ql[TOK*DD];
__device__ __align__(16) __nv_bfloat16 g_kh[TOK*KVD];
__device__ __align__(16) __nv_bfloat16 g_kl[TOK*KVD];
__device__ __align__(16) __nv_bfloat16 g_vh[TOK*KVD];
__device__ __align__(16) __nv_bfloat16 g_vl[TOK*KVD];

// ---------------------------------------------------------------------------
// helpers
// ---------------------------------------------------------------------------
__device__ __forceinline__ uint32_t smem_u32(const void* p) {
    uint32_t a;
    asm("{ .reg .u64 t; cvta.to.shared.u64 t, %1; cvt.u32.u64 %0, t; }" : "=r"(a) : "l"(p));
    return a;
}

#define CP_ASYNC16(dst, src) \
    asm volatile("cp.async.cg.shared.global [%0], [%1], 16;" :: "r"(dst), "l"(src))
#define CP_COMMIT()   asm volatile("cp.async.commit_group;" ::: "memory")
#define CP_WAIT(n)    asm volatile("cp.async.wait_group %0;" :: "n"(n) : "memory")

#define LDM_X4(r0, r1, r2, r3, addr) \
    asm volatile("ldmatrix.sync.aligned.m8n8.x4.shared.b16 {%0,%1,%2,%3}, [%4];" \
        : "=r"(r0), "=r"(r1), "=r"(r2), "=r"(r3) : "r"(addr))

#define LDM_X4T(r0, r1, r2, r3, addr) \
    asm volatile("ldmatrix.sync.aligned.m8n8.x4.trans.shared.b16 {%0,%1,%2,%3}, [%4];" \
        : "=r"(r0), "=r"(r1), "=r"(r2), "=r"(r3) : "r"(addr))

#define MMA16816(d, a, b) \
    asm volatile("mma.sync.aligned.m16n8k16.row.col.f32.bf16.bf16.f32 " \
        "{%0,%1,%2,%3},{%4,%5,%6,%7},{%8,%9},{%0,%1,%2,%3};" \
        : "+f"((d)[0]), "+f"((d)[1]), "+f"((d)[2]), "+f"((d)[3]) \
        : "r"((a)[0]), "r"((a)[1]), "r"((a)[2]), "r"((a)[3]), \
          "r"((b)[0]), "r"((b)[1]))

__device__ __forceinline__ uint32_t pack_bf16(float a, float b) {
    uint32_t d;
    asm("cvt.rn.bf16x2.f32 %0, %1, %2;" : "=r"(d) : "f"(b), "f"(a));
    return d;
}
__device__ __forceinline__ float ex2f(float x) {
    float r; asm("ex2.approx.f32 %0, %1;" : "=f"(r) : "f"(x)); return r;
}

// ---------------------------------------------------------------------------
// fp32 -> 3-term bf16 split (concatenated K)
// mode 0 (A-form): [hi | lo | hi]   mode 1 (B-form): [hi | hi | lo]
// ---------------------------------------------------------------------------
__global__ void split_bf16_kernel(const float* __restrict__ in,
                                  __nv_bfloat16* __restrict__ out,
                                  int K, int total4, int mode)
{
    int idx = blockIdx.x * blockDim.x + threadIdx.x;
    if (idx >= total4) return;
    float4 v = ((const float4*)in)[idx];
    int K4 = K >> 2;
    int r  = idx / K4;
    int k  = (idx - r * K4) << 2;
    float vv[4] = {v.x, v.y, v.z, v.w};
    __nv_bfloat16 h[4], l[4];
#pragma unroll
    for (int i = 0; i < 4; i++) {
        h[i] = __float2bfloat16(vv[i]);
        l[i] = __float2bfloat16(vv[i] - __bfloat162float(h[i]));
    }
    __nv_bfloat16* row = out + (size_t)r * (3*K);
    if (mode == 0) {
        *(uint2*)(row + k)       = *(uint2*)h;
        *(uint2*)(row + K + k)   = *(uint2*)l;
        *(uint2*)(row + 2*K + k) = *(uint2*)h;
    } else {
        *(uint2*)(row + k)       = *(uint2*)h;
        *(uint2*)(row + K + k)   = *(uint2*)h;
        *(uint2*)(row + 2*K + k) = *(uint2*)l;
    }
}

// ---------------------------------------------------------------------------
// bf16 MMA GEMM: C = A[M,K3] @ B[N,K3]^T
// CTA 128x128, BK=64, 256 threads (8 warps, 2m x 4n of 64x32), 3 stages, occ 2.
// MODE 0: fp32 C = acc + bias (bias in bq)
// MODE 1: fused QKV epilogue: route by column segment, rope q/k, hi/lo split.
// ---------------------------------------------------------------------------
#define CTM   128
#define CTN   128
#define GBK   64
#define NST   3
#define NCH   (K3 / GBK)            // 192
#define ROWB  144                   // 64 bf16 (128B) + 16B pad
#define ATILE (CTM * ROWB)          // 18432
#define BTILE (CTN * ROWB)          // 18432
#define STAGE (ATILE + BTILE)       // 36864
#define GSMEM (NST * STAGE)         // 110592

template<int MODE>
__global__ __launch_bounds__(256, 2) void gemm_mma(
    const __nv_bfloat16* __restrict__ A, const __nv_bfloat16* __restrict__ B,
    const float* __restrict__ bq, const float* __restrict__ bk,
    const float* __restrict__ bv,
    float* __restrict__ C, int N,
    const float* __restrict__ fc, const int* __restrict__ spos,
    __nv_bfloat16* __restrict__ qh, __nv_bfloat16* __restrict__ ql,
    __nv_bfloat16* __restrict__ kh, __nv_bfloat16* __restrict__ kl,
    __nv_bfloat16* __restrict__ vh, __nv_bfloat16* __restrict__ vl)
{
    extern __shared__ char smraw[];
    const int t    = threadIdx.x;
    const int lane = t & 31;
    const int wid  = t >> 5;
    const int wm   = wid & 1;
    const int wn   = wid >> 1;
    const int m0   = blockIdx.x * CTM;
    const int n0   = blockIdx.y * CTN;
    const uint32_t sb = smem_u32(smraw);

    float acc[4][4][4];
#pragma unroll
    for (int i = 0; i < 4; i++)
#pragma unroll
        for (int j = 0; j < 4; j++)
#pragma unroll
            for (int r = 0; r < 4; r++) acc[i][j][r] = 0.f;

    // per-thread cp.async mapping: 1024 16B-chunks for A, 1024 for B per stage
    // chunk id = t + i*256 (i<4 -> A, i>=4 -> B); row = id>>3, c = id&7
    const __nv_bfloat16* gsrc[8];
    uint32_t doff[8];
#pragma unroll
    for (int i = 0; i < 8; i++) {
        int id  = t + (i & 3) * 256;
        int row = id >> 3;
        int c8  = id & 7;
        doff[i] = row * ROWB + c8 * 16 + ((i < 4) ? 0u : (uint32_t)ATILE);
        gsrc[i] = (i < 4)
                ? A + (size_t)(m0 + row) * K3 + c8 * 8
                : B + (size_t)(n0 + row) * K3 + c8 * 8;
    }

#define LOAD_STAGE(st, k0) do {                                        \
    uint32_t base = sb + (st) * STAGE;                                 \
    _Pragma("unroll")                                                  \
    for (int i = 0; i < 8; i++)                                        \
        CP_ASYNC16(base + doff[i], gsrc[i] + (k0));                    \
} while (0)

#pragma unroll
    for (int s = 0; s < NST - 1; s++) {
        LOAD_STAGE(s, s * GBK);
        CP_COMMIT();
    }

    const uint32_t aoffs = (wm * 64 + (lane & 15)) * ROWB + ((lane >> 4) << 4);
    const uint32_t boffs = (wn * 32 + (lane & 15)) * ROWB + ((lane >> 4) << 4);

    int st = 0;
    for (int c = 0; c < NCH; c++) {
        CP_WAIT(1);
        __syncthreads();
        if (c + NST - 1 < NCH) {
            int st2 = st + 2; if (st2 >= NST) st2 -= NST;
            LOAD_STAGE(st2, (c + NST - 1) * GBK);
        }
        CP_COMMIT();

        const uint32_t ab = sb + st * STAGE;
        const uint32_t bb = ab + ATILE;

#pragma unroll
        for (int ks = 0; ks < 4; ks++) {
            uint32_t a[4][4];
            uint32_t bf[4][2];
#pragma unroll
            for (int mi = 0; mi < 4; mi++)
                LDM_X4(a[mi][0], a[mi][1], a[mi][2], a[mi][3],
                       ab + aoffs + mi * 16 * ROWB + ks * 32);
#pragma unroll
            for (int p = 0; p < 2; p++) {
                uint32_t r0, r1, r2, r3;
                LDM_X4(r0, r1, r2, r3, bb + boffs + p * 16 * ROWB + ks * 32);
                bf[2*p][0]   = r0; bf[2*p][1]   = r2;
                bf[2*p+1][0] = r1; bf[2*p+1][1] = r3;
            }
#pragma unroll
            for (int mi = 0; mi < 4; mi++)
#pragma unroll
                for (int ni = 0; ni < 4; ni++)
                    MMA16816(acc[mi][ni], a[mi], bf[ni]);
        }
        if (++st == NST) st = 0;
    }
#undef LOAD_STAGE

    if (MODE == 0) {
#pragma unroll
        for (int mi = 0; mi < 4; mi++) {
            int r0 = m0 + wm * 64 + mi * 16 + (lane >> 2);
#pragma unroll
            for (int ni = 0; ni < 4; ni++) {
                int col = n0 + wn * 32 + ni * 8 + (lane & 3) * 2;
                float2 bv2 = *(const float2*)(bq + col);
                float2 o0 = make_float2(acc[mi][ni][0] + bv2.x, acc[mi][ni][1] + bv2.y);
                float2 o1 = make_float2(acc[mi][ni][2] + bv2.x, acc[mi][ni][3] + bv2.y);
                *(float2*)(C + (size_t)r0 * N + col)       = o0;
                *(float2*)(C + (size_t)(r0 + 8) * N + col) = o1;
            }
        }
    } else {
        const int spv = spos[0];
        int seg, cbase;
        if (n0 < DD)            { seg = 0; cbase = 0; }
        else if (n0 < DD + KVD) { seg = 1; cbase = DD; }
        else                    { seg = 2; cbase = DD + KVD; }
        const float* bias = (seg == 0) ? bq : (seg == 1 ? bk : bv);
        __nv_bfloat16* dh = (seg == 0) ? qh : (seg == 1 ? kh : vh);
        __nv_bfloat16* dl = (seg == 0) ? ql : (seg == 1 ? kl : vl);
        const int   ldd = (seg == 0) ? DD : KVD;
        const float sc  = (seg == 0) ? QSCALE : 1.0f;

#pragma unroll
        for (int mi = 0; mi < 4; mi++) {
            int ra = m0 + wm * 64 + mi * 16 + (lane >> 2);
            int rb = ra + 8;
            int sa  = ra & (SS - 1);
            int sbt = rb & (SS - 1);
#pragma unroll
            for (int ni = 0; ni < 4; ni++) {
                int c  = n0 + wn * 32 + ni * 8 + (lane & 3) * 2;
                int cl = c - cbase;
                float b0 = bias[cl], b1 = bias[cl + 1];
                float v0 = acc[mi][ni][0] + b0, v1 = acc[mi][ni][1] + b1;
                float v2 = acc[mi][ni][2] + b0, v3 = acc[mi][ni][3] + b1;
                if (seg < 2) {
                    int p = (c & 127) >> 1;
                    float2 fa = *(const float2*)(fc + ((size_t)(spv + sa)  * 64 + p) * 2);
                    float2 fb = *(const float2*)(fc + ((size_t)(spv + sbt) * 64 + p) * 2);
                    float o0 = (v0 * fa.x - v1 * fa.y) * sc;
                    float o1 = (v0 * fa.y + v1 * fa.x) * sc;
                    float o2 = (v2 * fb.x - v3 * fb.y) * sc;
                    float o3 = (v2 * fb.y + v3 * fb.x) * sc;
                    v0 = o0; v1 = o1; v2 = o2; v3 = o3;
                }
                uint32_t h0 = pack_bf16(v0, v1);
                uint32_t h1 = pack_bf16(v2, v3);
                float f0 = __uint_as_float(h0 << 16), f1 = __uint_as_float(h0 & 0xffff0000u);
                float f2 = __uint_as_float(h1 << 16), f3 = __uint_as_float(h1 & 0xffff0000u);
                uint32_t l0 = pack_bf16(v0 - f0, v1 - f1);
                uint32_t l1 = pack_bf16(v2 - f2, v3 - f3);
                *(uint32_t*)(dh + (size_t)ra * ldd + cl) = h0;
                *(uint32_t*)(dl + (size_t)ra * ldd + cl) = l0;
                *(uint32_t*)(dh + (size_t)rb * ldd + cl) = h1;
                *(uint32_t*)(dl + (size_t)rb * ldd + cl) = l1;
            }
        }
    }
}

// ---------------------------------------------------------------------------
// Tensor-core causal flash attention (unchanged)
// ---------------------------------------------------------------------------
#define AROW     272
#define SQ_SZ    (128 * AROW)
#define KT_SZ    (64 * AROW)
#define STG_KH   0
#define STG_KL   17408
#define STG_VH   34816
#define STG_VL   52224
#define STG_SZ   (4 * KT_SZ)
#define ATT_SMEM (2 * SQ_SZ + 2 * STG_SZ)

__device__ __forceinline__ void att_load_kv(
    uint32_t dst, const __nv_bfloat16* khb, const __nv_bfloat16* klb,
    const __nv_bfloat16* vhb, const __nv_bfloat16* vlb, int n0, int t)
{
#pragma unroll
    for (int i = 0; i < 4; ++i) {
        int id = t + i * 256;
        int r  = id >> 4, c = id & 15;
        uint32_t o  = r * AROW + c * 16;
        size_t   go = (size_t)(n0 + r) * (KVH*HD) + c * 8;
        CP_ASYNC16(dst + STG_KH + o, khb + go);
        CP_ASYNC16(dst + STG_KL + o, klb + go);
        CP_ASYNC16(dst + STG_VH + o, vhb + go);
        CP_ASYNC16(dst + STG_VL + o, vlb + go);
    }
}

__global__ __launch_bounds__(256, 1) void attn_mma(
    const __nv_bfloat16* __restrict__ qh, const __nv_bfloat16* __restrict__ ql,
    const __nv_bfloat16* __restrict__ kh, const __nv_bfloat16* __restrict__ kl,
    const __nv_bfloat16* __restrict__ vh, const __nv_bfloat16* __restrict__ vl,
    __nv_bfloat16* __restrict__ cc)
{
    extern __shared__ char sm[];
    const int b   = blockIdx.z;
    const int h   = blockIdx.y;
    const int mb  = gridDim.x - 1 - blockIdx.x;
    const int m0  = mb * 128;
    const int kvh = h / GROUP;
    const int t    = threadIdx.x;
    const int lane = t & 31;
    const int w    = t >> 5;

    const uint32_t sb   = smem_u32(sm);
    const uint32_t sQh  = sb;
    const uint32_t sQl  = sb + SQ_SZ;
    const uint32_t sStg = sb + 2 * SQ_SZ;

    const __nv_bfloat16* qhb = qh + ((size_t)(b*SS + m0) * QH + h) * HD;
    const __nv_bfloat16* qlb = ql + ((size_t)(b*SS + m0) * QH + h) * HD;
    const __nv_bfloat16* khb = kh + ((size_t)b*SS*KVH + kvh) * HD;
    const __nv_bfloat16* klb = kl + ((size_t)b*SS*KVH + kvh) * HD;
    const __nv_bfloat16* vhb = vh + ((size_t)b*SS*KVH + kvh) * HD;
    const __nv_bfloat16* vlb = vl + ((size_t)b*SS*KVH + kvh) * HD;

#pragma unroll
    for (int i = 0; i < 8; ++i) {
        int id = t + i * 256;
        int r  = id >> 4, c = id & 15;
        uint32_t o  = r * AROW + c * 16;
        size_t   go = (size_t)r * (QH*HD) + c * 8;
        CP_ASYNC16(sQh + o, qhb + go);
        CP_ASYNC16(sQl + o, qlb + go);
    }
    att_load_kv(sStg, khb, klb, vhb, vlb, 0, t);
    CP_COMMIT();
    const int ntiles = 2 * mb + 2;
    if (ntiles > 1) att_load_kv(sStg + STG_SZ, khb, klb, vhb, vlb, 64, t);
    CP_COMMIT();

    const uint32_t qoff = (w * 16 + (lane & 15)) * AROW + ((lane >> 4) << 4);
    const uint32_t koff = (lane & 15) * AROW + ((lane >> 4) << 4);
    const int vrow = (lane & 7) + ((lane >> 4) << 3);
    const uint32_t vcol = ((lane >> 3) & 1) << 4;

    float O[16][4];
#pragma unroll
    for (int i = 0; i < 16; i++)
#pragma unroll
        for (int j = 0; j < 4; j++) O[i][j] = 0.f;
    float mx0 = -INFINITY, mx1 = -INFINITY, l0 = 0.f, l1 = 0.f;

    const int row0 = m0 + w * 16 + (lane >> 2);
    const int row1 = row0 + 8;
    const int wrow_hi = m0 + w * 16 + 15;
    const int wrow_lo = m0 + w * 16;

    for (int it = 0; it < ntiles; ++it) {
        const int n0 = it * 64;
        CP_WAIT(1);
        __syncthreads();
        const uint32_t stg = sStg + (it & 1) * STG_SZ;

        if (n0 <= wrow_hi) {
            float S[8][4];
#pragma unroll
            for (int i = 0; i < 8; i++)
#pragma unroll
                for (int j = 0; j < 4; j++) S[i][j] = 0.f;

#pragma unroll
            for (int ch = 0; ch < 8; ++ch) {
                uint32_t aq[4], al[4];
                LDM_X4(aq[0], aq[1], aq[2], aq[3], sQh + qoff + ch * 32);
                LDM_X4(al[0], al[1], al[2], al[3], sQl + qoff + ch * 32);
#pragma unroll
                for (int p = 0; p < 4; ++p) {
                    uint32_t h0,h1,h2,h3, e0,e1,e2,e3;
                    LDM_X4(h0,h1,h2,h3, stg + STG_KH + koff + p*(16*AROW) + ch*32);
                    LDM_X4(e0,e1,e2,e3, stg + STG_KL + koff + p*(16*AROW) + ch*32);
                    uint32_t bh0[2] = {h0, h2}, bh1[2] = {h1, h3};
                    uint32_t bl0[2] = {e0, e2}, bl1[2] = {e1, e3};
                    MMA16816(S[2*p],   aq, bh0);
                    MMA16816(S[2*p+1], aq, bh1);
                    MMA16816(S[2*p],   al, bh0);
                    MMA16816(S[2*p+1], al, bh1);
                    MMA16816(S[2*p],   aq, bl0);
                    MMA16816(S[2*p+1], aq, bl1);
                }
            }

            if (n0 + 63 > wrow_lo) {
#pragma unroll
                for (int p = 0; p < 8; ++p) {
                    int c = n0 + p * 8 + (lane & 3) * 2;
                    if (c     > row0) S[p][0] = -INFINITY;
                    if (c + 1 > row0) S[p][1] = -INFINITY;
                    if (c     > row1) S[p][2] = -INFINITY;
                    if (c + 1 > row1) S[p][3] = -INFINITY;
                }
            }

            float t0 = -INFINITY, t1 = -INFINITY;
#pragma unroll
            for (int p = 0; p < 8; ++p) {
                t0 = fmaxf(t0, fmaxf(S[p][0], S[p][1]));
                t1 = fmaxf(t1, fmaxf(S[p][2], S[p][3]));
            }
            t0 = fmaxf(t0, __shfl_xor_sync(0xffffffffu, t0, 1));
            t0 = fmaxf(t0, __shfl_xor_sync(0xffffffffu, t0, 2));
            t1 = fmaxf(t1, __shfl_xor_sync(0xffffffffu, t1, 1));
            t1 = fmaxf(t1, __shfl_xor_sync(0xffffffffu, t1, 2));
            float mn0 = fmaxf(mx0, t0), mn1 = fmaxf(mx1, t1);
            float cr0 = ex2f(mx0 - mn0), cr1 = ex2f(mx1 - mn1);
            mx0 = mn0; mx1 = mn1;

            float sa0 = 0.f, sa1 = 0.f;
#pragma unroll
            for (int p = 0; p < 8; ++p) {
                S[p][0] = ex2f(S[p][0] - mn0);
                S[p][1] = ex2f(S[p][1] - mn0);
                S[p][2] = ex2f(S[p][2] - mn1);
                S[p][3] = ex2f(S[p][3] - mn1);
                sa0 += S[p][0] + S[p][1];
                sa1 += S[p][2] + S[p][3];
            }
            sa0 += __shfl_xor_sync(0xffffffffu, sa0, 1);
            sa0 += __shfl_xor_sync(0xffffffffu, sa0, 2);
            sa1 += __shfl_xor_sync(0xffffffffu, sa1, 1);
            sa1 += __shfl_xor_sync(0xffffffffu, sa1, 2);
            l0 = l0 * cr0 + sa0;
            l1 = l1 * cr1 + sa1;

#pragma unroll
            for (int i = 0; i < 16; i++) {
                O[i][0] *= cr0; O[i][1] *= cr0;
                O[i][2] *= cr1; O[i][3] *= cr1;
            }

#pragma unroll
            for (int jc = 0; jc < 4; ++jc) {
                uint32_t ph[4], pl[4];
#pragma unroll
                for (int q2 = 0; q2 < 2; ++q2) {
                    float p0 = S[2*jc + q2][0], p1 = S[2*jc + q2][1];
                    float p2 = S[2*jc + q2][2], p3 = S[2*jc + q2][3];
                    uint32_t hp0 = pack_bf16(p0, p1);
                    uint32_t hp1 = pack_bf16(p2, p3);
                    float f0 = __uint_as_float(hp0 << 16);
                    float f1 = __uint_as_float(hp0 & 0xffff0000u);
                    float f2 = __uint_as_float(hp1 << 16);
                    float f3 = __uint_as_float(hp1 & 0xffff0000u);
                    ph[2*q2]   = hp0;  ph[2*q2+1] = hp1;
                    pl[2*q2]   = pack_bf16(p0 - f0, p1 - f1);
                    pl[2*q2+1] = pack_bf16(p2 - f2, p3 - f3);
                }
                const uint32_t vro = (jc * 16 + vrow) * AROW + vcol;
#pragma unroll
                for (int db = 0; db < 8; ++db) {
                    uint32_t a0,a1,a2,a3, c0,c1,c2,c3;
                    LDM_X4T(a0,a1,a2,a3, stg + STG_VH + vro + db * 32);
                    LDM_X4T(c0,c1,c2,c3, stg + STG_VL + vro + db * 32);
                    uint32_t bh0[2] = {a0, a2}, bh1[2] = {a1, a3};
                    uint32_t bl0[2] = {c0, c2}, bl1[2] = {c1, c3};
                    MMA16816(O[2*db],   ph, bh0);
                    MMA16816(O[2*db+1], ph, bh1);
                    MMA16816(O[2*db],   pl, bh0);
                    MMA16816(O[2*db+1], pl, bh1);
                    MMA16816(O[2*db],   ph, bl0);
                    MMA16816(O[2*db+1], ph, bl1);
                }
            }
        }

        __syncthreads();
        if (it + 2 < ntiles)
            att_load_kv(sStg + (it & 1) * STG_SZ, khb, klb, vhb, vlb, n0 + 128, t);
        CP_COMMIT();
    }

    float inv0 = 1.0f / l0, inv1 = 1.0f / l1;
    const size_t base0 = (size_t)(b * SS + row0) * K3;
    const size_t base1 = (size_t)(b * SS + row1) * K3;
    const int colb = h * 128 + (lane & 3) * 2;
#pragma unroll
    for (int dt = 0; dt < 16; ++dt) {
        int col = colb + dt * 8;
        float v0 = O[dt][0] * inv0, v1 = O[dt][1] * inv0;
        float v2 = O[dt][2] * inv1, v3 = O[dt][3] * inv1;
        uint32_t hi0 = pack_bf16(v0, v1);
        uint32_t hi1 = pack_bf16(v2, v3);
        float f0 = __uint_as_float(hi0 << 16), f1 = __uint_as_float(hi0 & 0xffff0000u);
        float f2 = __uint_as_float(hi1 << 16), f3 = __uint_as_float(hi1 & 0xffff0000u);
        uint32_t lo0 = pack_bf16(v0 - f0, v1 - f1);
        uint32_t lo1 = pack_bf16(v2 - f2, v3 - f3);
        *(uint32_t*)(cc + base0 + col)        = hi0;
        *(uint32_t*)(cc + base0 + DD + col)   = lo0;
        *(uint32_t*)(cc + base0 + 2*DD + col) = hi0;
        *(uint32_t*)(cc + base1 + col)        = hi1;
        *(uint32_t*)(cc + base1 + DD + col)   = lo1;
        *(uint32_t*)(cc + base1 + 2*DD + col) = hi1;
    }
}

// ---------------------------------------------------------------------------
// launch
// ---------------------------------------------------------------------------
extern "C" void kernel_launch(void* const* d_in, const int* in_sizes, int n_in,
                              void* d_out, int out_size)
{
    const float* xs   = (const float*)d_in[0];
    const int*   spos = (const int*)  d_in[1];
    const float* fc   = (const float*)d_in[2];
    const float* Wq   = (const float*)d_in[3];
    const float* bq   = (const float*)d_in[4];
    const float* Wk   = (const float*)d_in[5];
    const float* bk   = (const float*)d_in[6];
    const float* Wv   = (const float*)d_in[7];
    const float* bv   = (const float*)d_in[8];
    const float* Wo   = (const float*)d_in[9];
    const float* bo   = (const float*)d_in[10];
    float* out = (float*)d_out;

    __nv_bfloat16 *xc, *wqkv, *woc, *cc;
    __nv_bfloat16 *qhp, *qlp, *khp, *klp, *vhp, *vlp;
    cudaGetSymbolAddress((void**)&xc,   g_xc);
    cudaGetSymbolAddress((void**)&wqkv, g_wqkv);
    cudaGetSymbolAddress((void**)&woc,  g_woc);
    cudaGetSymbolAddress((void**)&cc,   g_cc);
    cudaGetSymbolAddress((void**)&qhp,  g_qh);
    cudaGetSymbolAddress((void**)&qlp,  g_ql);
    cudaGetSymbolAddress((void**)&khp,  g_kh);
    cudaGetSymbolAddress((void**)&klp,  g_kl);
    cudaGetSymbolAddress((void**)&vhp,  g_vh);
    cudaGetSymbolAddress((void**)&vlp,  g_vl);

    cudaFuncSetAttribute(gemm_mma<0>, cudaFuncAttributeMaxDynamicSharedMemorySize, GSMEM);
    cudaFuncSetAttribute(gemm_mma<1>, cudaFuncAttributeMaxDynamicSharedMemorySize, GSMEM);
    cudaFuncSetAttribute(attn_mma,    cudaFuncAttributeMaxDynamicSharedMemorySize, ATT_SMEM);

    // splits (launches 1-5)
    {
        int n;
        n = TOK*DD/4;  split_bf16_kernel<<<(n+255)/256, 256>>>(xs, xc, DD, n, 0);
        n = DD*DD/4;   split_bf16_kernel<<<(n+255)/256, 256>>>(Wq, wqkv, DD, n, 1);
        n = KVD*DD/4;  split_bf16_kernel<<<(n+255)/256, 256>>>(Wk, wqkv + (size_t)DD*K3, DD, n, 1);
        n = KVD*DD/4;  split_bf16_kernel<<<(n+255)/256, 256>>>(Wv, wqkv + (size_t)(DD+KVD)*K3, DD, n, 1);
        n = DD*DD/4;   split_bf16_kernel<<<(n+255)/256, 256>>>(Wo, woc, DD, n, 1);
    }

    // fused QKV projection + rope + split (launch 6)
    gemm_mma<1><<<dim3(TOK/CTM, NQKV/CTN), 256, GSMEM>>>(
        xc, wqkv, bq, bk, bv, nullptr, 0, fc, spos,
        qhp, qlp, khp, klp, vhp, vlp);

    // attention (launch 7)
    attn_mma<<<dim3(SS/128, QH, BB), 256, ATT_SMEM>>>(qhp, qlp, khp, klp, vhp, vlp, cc);

    // output projection (launch 8)
    gemm_mma<0><<<dim3(TOK/CTM, DD/CTN), 256, GSMEM>>>(
        cc, woc, bo, nullptr, nullptr, out, DD, nullptr, nullptr,
        nullptr, nullptr, nullptr, nullptr, nullptr, nullptr);
}